// round 7
// baseline (speedup 1.0000x reference)
#include <cuda_runtime.h>

#define BB 128
#define SS 512
#define KK 4
#define DD 300
#define CC 20
#define NN 10000

#define DSPLIT 3
#define DCH (DD / DSPLIT)            // 100
#define NB_PER_DC 125                // 125 blocks x 80 nodes = 10000
#define GRID (NB_PER_DC * DSPLIT)    // 375 blocks (<= 444 co-resident @ 3/SM)
#define TPB 320
#define SGRP 16

// Scratch + barrier state (deterministic; count returns to 0 each barrier)
__device__ float g_Pp[DSPLIT][NN * CC];      // split-D partials (2.4 MB)
__device__ float g_P[NN * CC];               // P = node_emb @ fc_w^T (800 KB)
__device__ unsigned int g_count = 0;
__device__ volatile unsigned int g_gen = 0;

struct P2 {
    int   sX[SS];                    // 2 KB
    float sNW[SS];                   // 2 KB
    int   sNX[SS * KK];              // 8 KB
    float sEW[SS * KK];              // 8 KB
    float sred[SGRP][CC];            // 1.25 KB
};
union Smem {
    float sF[CC * DCH];              // 8 KB (phase 1)
    P2    p2;                        // ~21.3 KB (phase 2)  -> 3 blocks/SM = 64 KB OK
};

__device__ __forceinline__ void grid_barrier()
{
    __syncthreads();
    if (threadIdx.x == 0) {
        const unsigned gen = g_gen;              // read BEFORE arriving
        __threadfence();                         // release my prior writes
        const unsigned old = atomicAdd(&g_count, 1u);
        if (old == GRID - 1) {
            g_count = 0;
            __threadfence();
            g_gen = gen + 1;
        } else {
            while (*(volatile unsigned*)&g_gen == gen) { }
        }
        __threadfence();                         // acquire others' writes
    }
    __syncthreads();
}

__global__ void __launch_bounds__(TPB, 3) fused_kernel(
    const int* __restrict__ X, const int* __restrict__ NX, const int* __restrict__ EW,
    const float* __restrict__ node_emb, const float* __restrict__ edge_w,
    const float* __restrict__ node_w, const float* __restrict__ fc_w,
    const float* __restrict__ fc_b, float* __restrict__ out)
{
    __shared__ Smem sm;
    const int t   = threadIdx.x;
    const int bid = blockIdx.x;

    // ------------- Phase 1: split-D partial GEMM (25 warps/SM) -------------
    // block -> (d-chunk dc, 80-node range); thread -> (node, 5-class group)
    {
        const int dc = bid / NB_PER_DC;
        const int nb = bid % NB_PER_DC;
        const int d0 = dc * DCH;

        for (int i = t; i < CC * DCH; i += TPB) {
            const int c = i / DCH, d = i % DCH;
            sm.sF[i] = fc_w[c * DD + d0 + d];
        }
        __syncthreads();

        const int n  = nb * 80 + (t >> 2);
        const int cg = t & 3;
        const float4* __restrict__ e4 = (const float4*)(node_emb + (size_t)n * DD + d0);
        const float4* __restrict__ f4 = (const float4*)(sm.sF) + cg * 5 * (DCH / 4);

        float acc[5] = {0.f, 0.f, 0.f, 0.f, 0.f};
        #pragma unroll 5
        for (int dq = 0; dq < DCH / 4; dq++) {   // 25 iters: 1 LDG.128 + 5 LDS.128 + 20 FFMA
            const float4 a = e4[dq];
            #pragma unroll
            for (int c5 = 0; c5 < 5; c5++) {
                const float4 fv = f4[c5 * (DCH / 4) + dq];
                acc[c5] += a.x * fv.x + a.y * fv.y + a.z * fv.z + a.w * fv.w;
            }
        }
        #pragma unroll
        for (int c5 = 0; c5 < 5; c5++)
            g_Pp[dc][n * CC + cg * 5 + c5] = acc[c5];
    }

    grid_barrier();

    // ------------- Phase 1b: reduce split-D partials (fixed order) ----------
    for (int i = bid * TPB + t; i < NN * CC; i += GRID * TPB)
        g_P[i] = g_Pp[0][i] + g_Pp[1][i] + g_Pp[2][i];

    grid_barrier();

    // ------------- Phase 2+3: per-b gather on P, reduce, softmax ------------
    if (bid >= BB) return;
    const int b = bid;

    for (int i = t; i < SS; i += TPB) {
        const int x = X[b * SS + i];
        sm.p2.sX[i]  = x;
        sm.p2.sNW[i] = node_w[x];
    }
    for (int i = t; i < SS * KK; i += TPB) sm.p2.sNX[i] = NX[b * SS * KK + i];
    for (int i = t; i < SS * KK; i += TPB) sm.p2.sEW[i] = edge_w[EW[b * SS * KK + i]];
    __syncthreads();

    const int g = t / CC, c = t % CC;
    float acc = 0.f;
    #pragma unroll 4
    for (int i = 0; i < SS / SGRP; i++) {        // 32 s-positions per thread
        const int s = g + i * SGRP;
        const float nw = sm.p2.sNW[s];
        float m = 0.f;
        #pragma unroll
        for (int k = 0; k < KK; k++)
            m += sm.p2.sEW[s * KK + k] * g_P[sm.p2.sNX[s * KK + k] * CC + c];
        acc += (1.f - nw) * m + nw * g_P[sm.p2.sX[s] * CC + c];
    }
    sm.p2.sred[g][c] = acc;
    __syncthreads();

    #pragma unroll
    for (int off = SGRP / 2; off > 0; off >>= 1) {
        if (g < off) sm.p2.sred[g][c] += sm.p2.sred[g + off][c];
        __syncthreads();
    }

    if (t < 32) {
        const float l = (t < CC) ? fmaxf(sm.p2.sred[0][t] + fc_b[t], 0.f) : -1e30f;
        float mx = l;
        #pragma unroll
        for (int o = 16; o; o >>= 1) mx = fmaxf(mx, __shfl_xor_sync(0xffffffffu, mx, o));
        const float e = (t < CC) ? __expf(l - mx) : 0.f;
        float sum = e;
        #pragma unroll
        for (int o = 16; o; o >>= 1) sum += __shfl_xor_sync(0xffffffffu, sum, o);
        if (t < CC) out[b * CC + t] = e / sum;
    }
}

extern "C" void kernel_launch(void* const* d_in, const int* in_sizes, int n_in,
                              void* d_out, int out_size)
{
    const int*   X        = (const int*)  d_in[0];
    const int*   NX       = (const int*)  d_in[1];
    const int*   EW       = (const int*)  d_in[2];
    const float* node_emb = (const float*)d_in[3];
    const float* edge_w   = (const float*)d_in[4];
    const float* node_w   = (const float*)d_in[5];
    const float* fc_w     = (const float*)d_in[6];
    const float* fc_b     = (const float*)d_in[7];
    float* out = (float*)d_out;

    fused_kernel<<<GRID, TPB>>>(X, NX, EW, node_emb, edge_w, node_w, fc_w, fc_b, out);
}

// round 8
// speedup vs baseline: 1.1452x; 1.1452x over previous
#include <cuda_runtime.h>

#define BB 128
#define SS 512
#define KK 4
#define DD 300
#define CC 20
#define NN 10000

// K1: thread = (dc 0..4, pair 0..15, cg 0..3) -> 320 threads, 32 nodes/block
#define DSPLIT 5
#define DCH (DD / DSPLIT)          // 60
#define P1_TPB 320
#define P1_NODES 32
#define P1_GRID ((NN + P1_NODES - 1) / P1_NODES)   // 313

// K2: one block per b
#define G_TPB 640
#define G_SGRP 32                  // 640 / CC

__device__ float g_P[NN * CC];     // P = node_emb @ fc_w^T (800 KB)

// ---------------------------------------------------------------------------
// K1: P[n,c] = sum_d E[n,d] * W[c,d], split-D in-block.
// 100k threads (~20 warps/SM). Per 4d: 2 LDG.128 + 5 LDS.128 + 40 FFMA.
// d-chunk partials reduced through smem, g_P written coalesced. One launch.
// ---------------------------------------------------------------------------
__global__ void __launch_bounds__(P1_TPB, 2) p_kernel(
    const float* __restrict__ node_emb, const float* __restrict__ fc_w)
{
    __shared__ float sF[DSPLIT * CC * DCH];          // 24 KB, [dc][c][d]
    __shared__ float sAcc[DSPLIT][P1_NODES * CC];    // 12.8 KB

    const int t = threadIdx.x;

    // Stage fc_w rearranged so each d-chunk slice is contiguous & 16B aligned
    for (int i = t; i < DSPLIT * CC * DCH; i += P1_TPB) {
        const int dc = i / (CC * DCH);
        const int r  = i % (CC * DCH);
        const int c  = r / DCH, d = r % DCH;
        sF[i] = fc_w[c * DD + dc * DCH + d];
    }
    __syncthreads();

    const int dc = t / 64;                 // 0..4
    const int w  = t % 64;
    const int pr = w >> 2;                 // 0..15 node-pair
    const int cg = w & 3;                  // 0..3  class-group (5 classes)
    const int n0 = blockIdx.x * P1_NODES + pr * 2;
    const int d0 = dc * DCH;

    if (n0 < NN) {                         // NN even -> pair never splits
        const float4* __restrict__ e0 = (const float4*)(node_emb + (size_t)n0 * DD + d0);
        const float4* __restrict__ e1 = (const float4*)(node_emb + (size_t)(n0 + 1) * DD + d0);
        const float4* __restrict__ f4 = (const float4*)(sF + dc * CC * DCH + cg * 5 * DCH);

        float a0[5] = {0.f, 0.f, 0.f, 0.f, 0.f};
        float a1[5] = {0.f, 0.f, 0.f, 0.f, 0.f};
        #pragma unroll
        for (int dq = 0; dq < DCH / 4; dq++) {       // 15 iters
            const float4 v0 = e0[dq];
            const float4 v1 = e1[dq];
            #pragma unroll
            for (int c5 = 0; c5 < 5; c5++) {
                const float4 fv = f4[c5 * (DCH / 4) + dq];
                a0[c5] += v0.x * fv.x + v0.y * fv.y + v0.z * fv.z + v0.w * fv.w;
                a1[c5] += v1.x * fv.x + v1.y * fv.y + v1.z * fv.z + v1.w * fv.w;
            }
        }
        #pragma unroll
        for (int c5 = 0; c5 < 5; c5++) {
            sAcc[dc][(pr * 2    ) * CC + cg * 5 + c5] = a0[c5];
            sAcc[dc][(pr * 2 + 1) * CC + cg * 5 + c5] = a1[c5];
        }
    }
    __syncthreads();

    // Reduce 5 d-chunk partials, write g_P coalesced (640 floats/block)
    const int base = blockIdx.x * P1_NODES * CC;
    for (int i = t; i < P1_NODES * CC; i += P1_TPB) {
        if (base + i < NN * CC) {
            float s = sAcc[0][i];
            #pragma unroll
            for (int d = 1; d < DSPLIT; d++) s += sAcc[d][i];
            g_P[base + i] = s;
        }
    }
}

// ---------------------------------------------------------------------------
// K2: per-b gather on P + fixed-order reduce + bias/relu/softmax. One launch.
// ---------------------------------------------------------------------------
__global__ void __launch_bounds__(G_TPB) gather_kernel(
    const int* __restrict__ X, const int* __restrict__ NX, const int* __restrict__ EW,
    const float* __restrict__ edge_w, const float* __restrict__ node_w,
    const float* __restrict__ fc_b, float* __restrict__ out)
{
    __shared__ int   sX[SS];               // 2 KB
    __shared__ float sNW[SS];              // 2 KB
    __shared__ int   sNX[SS * KK];         // 8 KB
    __shared__ float sEW[SS * KK];         // 8 KB
    __shared__ float sred[G_SGRP][CC];     // 2.5 KB

    const int b = blockIdx.x;
    const int t = threadIdx.x;

    // Stage all indices/scalars: 2048 random edge_w DRAM gathers over 640
    // threads -> 3.2 rounds, very high MLP.
    for (int i = t; i < SS * KK; i += G_TPB) sEW[i] = edge_w[EW[b * SS * KK + i]];
    for (int i = t; i < SS * KK; i += G_TPB) sNX[i] = NX[b * SS * KK + i];
    for (int i = t; i < SS; i += G_TPB) {
        const int x = X[b * SS + i];
        sX[i]  = x;
        sNW[i] = node_w[x];
    }
    __syncthreads();

    // thread (g, c): class c over 16 s-positions; 80B row-gathers on P (L2)
    const int g = t / CC, c = t % CC;
    float acc = 0.f;
    #pragma unroll 4
    for (int i = 0; i < SS / G_SGRP; i++) {        // 16
        const int s = g + i * G_SGRP;
        const float nw = sNW[s];
        float m = 0.f;
        #pragma unroll
        for (int k = 0; k < KK; k++)
            m += sEW[s * KK + k] * __ldg(&g_P[sNX[s * KK + k] * CC + c]);
        acc += (1.f - nw) * m + nw * __ldg(&g_P[sX[s] * CC + c]);
    }
    sred[g][c] = acc;
    __syncthreads();

    // Fixed-order tree reduce over 32 s-groups -> deterministic
    #pragma unroll
    for (int off = G_SGRP / 2; off > 0; off >>= 1) {
        if (g < off) sred[g][c] += sred[g + off][c];
        __syncthreads();
    }

    // warp 0: bias + relu + softmax over 20 classes
    if (t < 32) {
        const float l = (t < CC) ? fmaxf(sred[0][t] + fc_b[t], 0.f) : -1e30f;
        float mx = l;
        #pragma unroll
        for (int o = 16; o; o >>= 1) mx = fmaxf(mx, __shfl_xor_sync(0xffffffffu, mx, o));
        const float e = (t < CC) ? __expf(l - mx) : 0.f;
        float sum = e;
        #pragma unroll
        for (int o = 16; o; o >>= 1) sum += __shfl_xor_sync(0xffffffffu, sum, o);
        if (t < CC) out[b * CC + t] = e / sum;
    }
}

// ---------------------------------------------------------------------------
extern "C" void kernel_launch(void* const* d_in, const int* in_sizes, int n_in,
                              void* d_out, int out_size)
{
    const int*   X        = (const int*)  d_in[0];
    const int*   NX       = (const int*)  d_in[1];
    const int*   EW       = (const int*)  d_in[2];
    const float* node_emb = (const float*)d_in[3];
    const float* edge_w   = (const float*)d_in[4];
    const float* node_w   = (const float*)d_in[5];
    const float* fc_w     = (const float*)d_in[6];
    const float* fc_b     = (const float*)d_in[7];
    float* out = (float*)d_out;

    p_kernel<<<P1_GRID, P1_TPB>>>(node_emb, fc_w);
    gather_kernel<<<BB, G_TPB>>>(X, NX, EW, edge_w, node_w, fc_b, out);
}